// round 3
// baseline (speedup 1.0000x reference)
#include <cuda_runtime.h>

#define GRID     128
#define NTHREADS 256
#define NT       4096     // B*S tokens

// ---- device globals (no allocation allowed) ----
__device__ float g_QKV[NT * 192];      // 3 MB
__device__ float g_A[NT * 64];         // 1 MB
__device__ float g_TEMB[4096 * 64];    // temb per step (supports up to 4096 loops)
__device__ unsigned g_arrive;
__device__ volatile unsigned g_release;

// ---- smem layout (floats) ----
#define OFF_WQKV 0            // 64*192 = 12288
#define OFF_WO   12288        // 64*64  = 4096
#define OFF_WFC  16384        // 64*256 = 16384
#define OFF_WPR  32768        // 256*64 = 16384
#define OFF_BIAS 49152        // 960
#define OFF_X    50112        // 32*64 = 2048
#define OFF_R    52160        // 5376 scratch (K/V tiles, softmax P, h/hid)
#define SMEM_FLOATS 57536
#define SMEM_BYTES (SMEM_FLOATS * 4)   // 230144 <= 232448

__device__ __forceinline__ void grid_sync(unsigned gen) {
    __syncthreads();
    if (threadIdx.x == 0) {
        __threadfence();
        unsigned prev = atomicAdd(&g_arrive, 1u);
        if (prev == gen * GRID - 1u) {
            __threadfence();
            g_release = gen;                       // volatile store
        } else {
            while (*(volatile unsigned*)&g_release < gen) { __nanosleep(64); }
        }
        __threadfence();
    }
    __syncthreads();
}

extern "C" __global__ void __launch_bounds__(NTHREADS, 1)
lt37349035606833_kernel(
    const int*   __restrict__ idx,   const int*   __restrict__ nloops_p,
    const float* __restrict__ wte,   const float* __restrict__ wpe,
    const float* __restrict__ tw1,   const float* __restrict__ tb1,
    const float* __restrict__ tw2,   const float* __restrict__ tb2,
    const float* __restrict__ ln1g_, const float* __restrict__ ln1b_,
    const float* __restrict__ wqkv_, const float* __restrict__ bqkv_,
    const float* __restrict__ wo_,   const float* __restrict__ bo_,
    const float* __restrict__ ln2g_, const float* __restrict__ ln2b_,
    const float* __restrict__ wfc_,  const float* __restrict__ bfc_,
    const float* __restrict__ wpr_,  const float* __restrict__ bpr_,
    const float* __restrict__ lnfg_, const float* __restrict__ lnfb_,
    float* __restrict__ out)
{
    extern __shared__ float sm[];
    const int tid = threadIdx.x;
    const int blk = blockIdx.x;
    const int w = tid >> 5, l = tid & 31;
    const int nloops = *nloops_p;
    unsigned gen = g_release;          // generation base (persists across graph replays)

    // ---- stage all weights/biases into smem ----
    for (int i = tid; i < 12288; i += NTHREADS) sm[OFF_WQKV + i] = wqkv_[i];
    for (int i = tid; i < 4096;  i += NTHREADS) sm[OFF_WO   + i] = wo_[i];
    for (int i = tid; i < 16384; i += NTHREADS) sm[OFF_WFC  + i] = wfc_[i];
    for (int i = tid; i < 16384; i += NTHREADS) sm[OFF_WPR  + i] = wpr_[i];
    if (tid < 192) sm[OFF_BIAS + tid] = bqkv_[tid];
    sm[OFF_BIAS + 256 + tid] = bfc_[tid];                 // 256 entries, tid<256 always
    if (tid < 64) {
        sm[OFF_BIAS + 192 + tid] = bo_[tid];
        sm[OFF_BIAS + 512 + tid] = bpr_[tid];
        sm[OFF_BIAS + 576 + tid] = ln1g_[tid];
        sm[OFF_BIAS + 640 + tid] = ln1b_[tid];
        sm[OFF_BIAS + 704 + tid] = ln2g_[tid];
        sm[OFF_BIAS + 768 + tid] = ln2b_[tid];
        sm[OFF_BIAS + 832 + tid] = lnfg_[tid];
        sm[OFF_BIAS + 896 + tid] = lnfb_[tid];
    }

    // ---- initial x tile: wte[idx] + wpe ----
    const int t0 = blk * 32;
    for (int i = tid; i < 2048; i += NTHREADS) {
        int t = i >> 6, d = i & 63;
        int tok = t0 + t;
        sm[OFF_X + i] = wte[idx[tok] * 64 + d] + wpe[(tok & 127) * 64 + d];
    }
    __syncthreads();

    // ---- precompute temb for every step (block s computes step s, s+128, ...) ----
    float* sR = sm + OFF_R;
    for (int s = blk; s < nloops; s += GRID) {
        float tt = (float)s;
        if (tid < 128) {
            float f = __expf(-9.2103403719761836f * (float)tid / 128.0f);
            float a = tt * f;
            sR[tid]       = cosf(a);
            sR[128 + tid] = sinf(a);
        }
        __syncthreads();
        for (int j = tid; j < 1024; j += NTHREADS) {
            float z = tb1[j];
            for (int k = 0; k < 256; ++k) z += sR[k] * tw1[k * 1024 + j];
            sR[256 + j] = z / (1.0f + __expf(-z));        // silu
        }
        __syncthreads();
        if (tid < 64) {
            float z = tb2[tid];
            for (int k = 0; k < 1024; ++k) z += sR[256 + k] * tw2[k * 64 + tid];
            g_TEMB[s * 64 + tid] = z;
        }
        __syncthreads();
    }
    grid_sync(++gen);

    const int bb = blk >> 2, hh = blk & 3;
    const int tbatt = bb * 128;
    float* sX  = sm + OFF_X;
    const float* sWq = sm + OFF_WQKV;
    const float* sWo = sm + OFF_WO;
    const float* sWf = sm + OFF_WFC;
    const float* sWp = sm + OFF_WPR;
    const float* sBq = sm + OFF_BIAS;
    const float* sBo = sm + OFF_BIAS + 192;
    const float* sBf = sm + OFF_BIAS + 256;
    const float* sBp = sm + OFF_BIAS + 512;
    const float* sL1g = sm + OFF_BIAS + 576, *sL1b = sm + OFF_BIAS + 640;
    const float* sL2g = sm + OFF_BIAS + 704, *sL2b = sm + OFF_BIAS + 768;
    const float* sLfg = sm + OFF_BIAS + 832, *sLfb = sm + OFF_BIAS + 896;

    for (int it = 0; it < nloops; ++it) {
        // ================= Phase A: x += temb; LN1; QKV =================
        {
            float* hA = sR + w * 256;
            const float* temb = g_TEMB + it * 64;
            #pragma unroll
            for (int t = 0; t < 4; ++t) {
                int lt = w * 4 + t;
                float x0 = sX[lt * 64 + l]      + temb[l];
                float x1 = sX[lt * 64 + 32 + l] + temb[32 + l];
                sX[lt * 64 + l]      = x0;
                sX[lt * 64 + 32 + l] = x1;
                float s1 = x0 + x1, s2 = x0 * x0 + x1 * x1;
                #pragma unroll
                for (int o = 16; o; o >>= 1) {
                    s1 += __shfl_xor_sync(0xffffffffu, s1, o);
                    s2 += __shfl_xor_sync(0xffffffffu, s2, o);
                }
                float mu = s1 * (1.0f / 64.0f);
                float rs = rsqrtf(s2 * (1.0f / 64.0f) - mu * mu + 1e-5f);
                hA[t * 64 + l]      = (x0 - mu) * rs * sL1g[l]      + sL1b[l];
                hA[t * 64 + 32 + l] = (x1 - mu) * rs * sL1g[32 + l] + sL1b[32 + l];
            }
            __syncwarp();
            float acc[6][4];
            #pragma unroll
            for (int s2 = 0; s2 < 6; ++s2)
                #pragma unroll
                for (int t = 0; t < 4; ++t) acc[s2][t] = 0.f;
            #pragma unroll 4
            for (int k = 0; k < 64; ++k) {
                float h0 = hA[k], h1v = hA[64 + k], h2 = hA[128 + k], h3 = hA[192 + k];
                #pragma unroll
                for (int s2 = 0; s2 < 6; ++s2) {
                    float wv = sWq[k * 192 + 32 * s2 + l];
                    acc[s2][0] += wv * h0; acc[s2][1] += wv * h1v;
                    acc[s2][2] += wv * h2; acc[s2][3] += wv * h3;
                }
            }
            #pragma unroll
            for (int t = 0; t < 4; ++t) {
                int tok = t0 + w * 4 + t;
                #pragma unroll
                for (int s2 = 0; s2 < 6; ++s2)
                    g_QKV[tok * 192 + 32 * s2 + l] = acc[s2][t] + sBq[32 * s2 + l];
            }
        }
        grid_sync(++gen);

        // ================= Phase B: attention for (bb, hh) =================
        // stage K,V (pitch 17 to kill bank conflicts); reads MUST bypass L1 (.cg)
        for (int i = tid; i < 2048; i += NTHREADS) {
            int kt = i >> 4, d = i & 15;
            sR[kt * 17 + d]        = __ldcg(&g_QKV[(tbatt + kt) * 192 + 64  + hh * 16 + d]);
            sR[2176 + kt * 17 + d] = __ldcg(&g_QKV[(tbatt + kt) * 192 + 128 + hh * 16 + d]);
        }
        __syncthreads();
        {
            float* sP = sR + 4352 + w * 128;
            for (int r = 0; r < 16; ++r) {
                int qt = w * 16 + r;
                const float* qptr = g_QKV + (tbatt + qt) * 192 + hh * 16;
                float q[16];
                #pragma unroll
                for (int d = 0; d < 16; ++d) q[d] = __ldcg(qptr + d);
                float sc0 = 0.f, sc1 = 0.f, sc2 = 0.f, sc3 = 0.f;
                #pragma unroll
                for (int d = 0; d < 16; ++d) {
                    sc0 += q[d] * sR[l * 17 + d];
                    sc1 += q[d] * sR[(l + 32) * 17 + d];
                    sc2 += q[d] * sR[(l + 64) * 17 + d];
                    sc3 += q[d] * sR[(l + 96) * 17 + d];
                }
                sc0 = sc0 * 0.25f + ((l      <= qt) ? 0.f : -1e9f);
                sc1 = sc1 * 0.25f + ((l + 32 <= qt) ? 0.f : -1e9f);
                sc2 = sc2 * 0.25f + ((l + 64 <= qt) ? 0.f : -1e9f);
                sc3 = sc3 * 0.25f + ((l + 96 <= qt) ? 0.f : -1e9f);
                float mx = fmaxf(fmaxf(sc0, sc1), fmaxf(sc2, sc3));
                #pragma unroll
                for (int o = 16; o; o >>= 1) mx = fmaxf(mx, __shfl_xor_sync(0xffffffffu, mx, o));
                float e0 = __expf(sc0 - mx), e1 = __expf(sc1 - mx);
                float e2 = __expf(sc2 - mx), e3 = __expf(sc3 - mx);
                float es = e0 + e1 + e2 + e3;
                #pragma unroll
                for (int o = 16; o; o >>= 1) es += __shfl_xor_sync(0xffffffffu, es, o);
                float inv = 1.0f / es;
                sP[l]      = e0 * inv;
                sP[l + 32] = e1 * inv;
                sP[l + 64] = e2 * inv;
                sP[l + 96] = e3 * inv;
                __syncwarp();
                int d = l & 15, half = l >> 4;
                const float* Vh = sR + 2176 + half * 64 * 17;
                const float* Ph = sP + half * 64;
                float ov = 0.f;
                #pragma unroll 8
                for (int k2 = 0; k2 < 64; ++k2) ov += Ph[k2] * Vh[k2 * 17 + d];
                ov += __shfl_xor_sync(0xffffffffu, ov, 16);
                if (half == 0) g_A[(tbatt + qt) * 64 + hh * 16 + d] = ov;
                __syncwarp();
            }
        }
        grid_sync(++gen);

        // ================= Phase C: o-proj + LN2 + MLP =================
        {
            float* hW = sR + w * 640;   // h[2][64] @0, hid[2][256] @128
            #pragma unroll
            for (int gp = 0; gp < 2; ++gp) {
                int lta = w * 4 + gp * 2, ltb = lta + 1;
                const float* Aa = g_A + (t0 + lta) * 64;
                const float* Ab = g_A + (t0 + ltb) * 64;
                float o00 = 0, o01 = 0, o10 = 0, o11 = 0;
                #pragma unroll 4
                for (int k = 0; k < 64; ++k) {
                    float a0 = __ldcg(Aa + k), a1 = __ldcg(Ab + k);   // bypass stale L1
                    float w0 = sWo[k * 64 + l], w1 = sWo[k * 64 + 32 + l];
                    o00 += w0 * a0; o01 += w0 * a1; o10 += w1 * a0; o11 += w1 * a1;
                }
                float xa0 = sX[lta * 64 + l]      + 0.1f * (o00 + sBo[l]);
                float xa1 = sX[lta * 64 + 32 + l] + 0.1f * (o10 + sBo[32 + l]);
                float xb0 = sX[ltb * 64 + l]      + 0.1f * (o01 + sBo[l]);
                float xb1 = sX[ltb * 64 + 32 + l] + 0.1f * (o11 + sBo[32 + l]);
                float s1a = xa0 + xa1, s2a = xa0 * xa0 + xa1 * xa1;
                float s1b = xb0 + xb1, s2b = xb0 * xb0 + xb1 * xb1;
                #pragma unroll
                for (int o = 16; o; o >>= 1) {
                    s1a += __shfl_xor_sync(0xffffffffu, s1a, o);
                    s2a += __shfl_xor_sync(0xffffffffu, s2a, o);
                    s1b += __shfl_xor_sync(0xffffffffu, s1b, o);
                    s2b += __shfl_xor_sync(0xffffffffu, s2b, o);
                }
                float mua = s1a * (1.f/64.f), rsa = rsqrtf(s2a * (1.f/64.f) - mua * mua + 1e-5f);
                float mub = s1b * (1.f/64.f), rsb = rsqrtf(s2b * (1.f/64.f) - mub * mub + 1e-5f);
                hW[l]      = (xa0 - mua) * rsa * sL2g[l]      + sL2b[l];
                hW[32 + l] = (xa1 - mua) * rsa * sL2g[32 + l] + sL2b[32 + l];
                hW[64 + l] = (xb0 - mub) * rsb * sL2g[l]      + sL2b[l];
                hW[96 + l] = (xb1 - mub) * rsb * sL2g[32 + l] + sL2b[32 + l];
                __syncwarp();
                float fa[8][2];
                #pragma unroll
                for (int s2 = 0; s2 < 8; ++s2) { fa[s2][0] = 0.f; fa[s2][1] = 0.f; }
                #pragma unroll 4
                for (int k = 0; k < 64; ++k) {
                    float h0 = hW[k], h1v = hW[64 + k];
                    #pragma unroll
                    for (int s2 = 0; s2 < 8; ++s2) {
                        float wv = sWf[k * 256 + 32 * s2 + l];
                        fa[s2][0] += wv * h0; fa[s2][1] += wv * h1v;
                    }
                }
                __syncwarp();
                #pragma unroll
                for (int s2 = 0; s2 < 8; ++s2) {
                    #pragma unroll
                    for (int t = 0; t < 2; ++t) {
                        float z = fa[s2][t] + sBf[32 * s2 + l];
                        float u = 0.7978845608028654f * (z + 0.044715f * z * z * z);
                        float e2u = __expf(2.0f * u);
                        float th = 1.0f - 2.0f / (e2u + 1.0f);   // tanh(u)
                        hW[128 + t * 256 + 32 * s2 + l] = 0.5f * z * (1.0f + th);
                    }
                }
                __syncwarp();
                float p00 = 0, p01 = 0, p10 = 0, p11 = 0;
                #pragma unroll 4
                for (int k = 0; k < 256; ++k) {
                    float h0 = hW[128 + k], h1v = hW[384 + k];
                    float w0 = sWp[k * 64 + l], w1 = sWp[k * 64 + 32 + l];
                    p00 += w0 * h0; p01 += w0 * h1v; p10 += w1 * h0; p11 += w1 * h1v;
                }
                sX[lta * 64 + l]      = xa0 + 0.1f * (p00 + sBp[l]);
                sX[lta * 64 + 32 + l] = xa1 + 0.1f * (p10 + sBp[32 + l]);
                sX[ltb * 64 + l]      = xb0 + 0.1f * (p01 + sBp[l]);
                sX[ltb * 64 + 32 + l] = xb1 + 0.1f * (p11 + sBp[32 + l]);
                __syncwarp();
            }
        }
        __syncthreads();   // sR (hW regions) must drain before next Phase A reuses sR
    }

    // ================= final LN -> out =================
    #pragma unroll
    for (int t = 0; t < 4; ++t) {
        int lt = w * 4 + t;
        float x0 = sX[lt * 64 + l], x1 = sX[lt * 64 + 32 + l];
        float s1 = x0 + x1, s2 = x0 * x0 + x1 * x1;
        #pragma unroll
        for (int o = 16; o; o >>= 1) {
            s1 += __shfl_xor_sync(0xffffffffu, s1, o);
            s2 += __shfl_xor_sync(0xffffffffu, s2, o);
        }
        float mu = s1 * (1.f/64.f);
        float rs = rsqrtf(s2 * (1.f/64.f) - mu * mu + 1e-5f);
        out[(t0 + lt) * 64 + l]      = (x0 - mu) * rs * sLfg[l]      + sLfb[l];
        out[(t0 + lt) * 64 + 32 + l] = (x1 - mu) * rs * sLfg[32 + l] + sLfb[32 + l];
    }
}

extern "C" void kernel_launch(void* const* d_in, const int* in_sizes, int n_in,
                              void* d_out, int out_size)
{
    (void)in_sizes; (void)n_in; (void)out_size;
    cudaFuncSetAttribute(lt37349035606833_kernel,
                         cudaFuncAttributeMaxDynamicSharedMemorySize, SMEM_BYTES);
    lt37349035606833_kernel<<<GRID, NTHREADS, SMEM_BYTES>>>(
        (const int*)  d_in[0],  (const int*)  d_in[1],
        (const float*)d_in[2],  (const float*)d_in[3],
        (const float*)d_in[4],  (const float*)d_in[5],
        (const float*)d_in[6],  (const float*)d_in[7],
        (const float*)d_in[8],  (const float*)d_in[9],
        (const float*)d_in[10], (const float*)d_in[11],
        (const float*)d_in[12], (const float*)d_in[13],
        (const float*)d_in[14], (const float*)d_in[15],
        (const float*)d_in[16], (const float*)d_in[17],
        (const float*)d_in[18], (const float*)d_in[19],
        (const float*)d_in[20], (const float*)d_in[21],
        (float*)d_out);
}

// round 4
// speedup vs baseline: 1.0953x; 1.0953x over previous
#include <cuda_runtime.h>

#define GRID     128
#define NTHREADS 512
#define NT       4096     // B*S tokens

// ---- device globals (no allocation allowed) ----
__device__ float g_QKV[NT * 192];      // [tok][192]  (Q|K|V)
__device__ float g_A[NT * 64];         // attention output [tok][64]
__device__ float g_TEMB[4096 * 64];    // temb per step
__device__ unsigned g_arrive;
__device__ volatile unsigned g_release;

// ---- smem layout (floats) ----
#define OFF_WQKV 0            // [k][192]      12288
#define OFF_WFC  12288        // [k][256]      16384
#define OFF_WPR  28672        // [k(256)][64]  16384
#define OFF_B    45056        // 704: bqkv[192] bfc[256] ln1g ln1b ln2g ln2b
#define OFF_X    45760        // 32 tokens, pitch 65 = 2080
#define OFF_R    47840        // 10240 scratch
#define SMEM_FLOATS 58080
#define SMEM_BYTES (SMEM_FLOATS * 4)   // 232320 <= 232448

__device__ __forceinline__ void grid_sync(unsigned gen) {
    __syncthreads();
    if (threadIdx.x == 0) {
        __threadfence();
        unsigned prev = atomicAdd(&g_arrive, 1u);
        if (prev == gen * GRID - 1u) {
            __threadfence();
            g_release = gen;
        } else {
            while (*(volatile unsigned*)&g_release < gen) { __nanosleep(32); }
        }
        __threadfence();
    }
    __syncthreads();
}

extern "C" __global__ void __launch_bounds__(NTHREADS, 1)
lt37349035606833_kernel(
    const int*   __restrict__ idx,   const int*   __restrict__ nloops_p,
    const float* __restrict__ wte,   const float* __restrict__ wpe,
    const float* __restrict__ tw1,   const float* __restrict__ tb1,
    const float* __restrict__ tw2,   const float* __restrict__ tb2,
    const float* __restrict__ ln1g_, const float* __restrict__ ln1b_,
    const float* __restrict__ wqkv_, const float* __restrict__ bqkv_,
    const float* __restrict__ wo_,   const float* __restrict__ bo_,
    const float* __restrict__ ln2g_, const float* __restrict__ ln2b_,
    const float* __restrict__ wfc_,  const float* __restrict__ bfc_,
    const float* __restrict__ wpr_,  const float* __restrict__ bpr_,
    const float* __restrict__ lnfg_, const float* __restrict__ lnfb_,
    float* __restrict__ out)
{
    extern __shared__ float sm[];
    const int tid = threadIdx.x;
    const int blk = blockIdx.x;
    const int w = tid >> 5, l = tid & 31;
    const int nloops = *nloops_p;
    unsigned gen = g_release;

    // ---- stage weights/biases into smem ----
    for (int i = tid; i < 12288; i += NTHREADS) sm[OFF_WQKV + i] = wqkv_[i];
    for (int i = tid; i < 16384; i += NTHREADS) {
        sm[OFF_WFC + i] = wfc_[i];
        sm[OFF_WPR + i] = wpr_[i];
    }
    if (tid < 192)                sm[OFF_B + tid] = bqkv_[tid];
    if (tid >= 192 && tid < 448)  sm[OFF_B + tid] = bfc_[tid - 192];
    if (tid < 64) {
        sm[OFF_B + 448 + tid] = ln1g_[tid];
        sm[OFF_B + 512 + tid] = ln1b_[tid];
        sm[OFF_B + 576 + tid] = ln2g_[tid];
        sm[OFF_B + 640 + tid] = ln2b_[tid];
    }
    const float rbo0 = __ldg(bo_ + l),  rbo1 = __ldg(bo_ + 32 + l);
    const float rbp0 = __ldg(bpr_ + l), rbp1 = __ldg(bpr_ + 32 + l);

    // ---- initial x tile (pitch 65) ----
    const int t0 = blk * 32;
    for (int i = tid; i < 2048; i += NTHREADS) {
        int t = i >> 6, d = i & 63;
        int tok = t0 + t;
        sm[OFF_X + t * 65 + d] = wte[idx[tok] * 64 + d] + wpe[(tok & 127) * 64 + d];
    }
    __syncthreads();

    // ---- precompute temb for all steps ----
    float* sR = sm + OFF_R;
    for (int s = blk; s < nloops; s += GRID) {
        float tt = (float)s;
        if (tid < 128) {
            float f = __expf(-9.2103403719761836f * (float)tid / 128.0f);
            float a = tt * f;
            sR[tid]       = cosf(a);
            sR[128 + tid] = sinf(a);
        }
        __syncthreads();
        for (int j = tid; j < 1024; j += NTHREADS) {
            float z = tb1[j];
            for (int k = 0; k < 256; ++k) z += sR[k] * tw1[k * 1024 + j];
            sR[256 + j] = z / (1.0f + __expf(-z));
        }
        __syncthreads();
        if (tid < 64) {
            float z = tb2[tid];
            for (int k = 0; k < 1024; ++k) z += sR[256 + k] * tw2[k * 64 + tid];
            g_TEMB[s * 64 + tid] = z;
        }
        __syncthreads();
    }
    grid_sync(++gen);

    const int bb = blk >> 2, hh = blk & 3;
    const int tbatt = bb * 128;
    float* sX  = sm + OFF_X;
    const float* sWq = sm + OFF_WQKV;
    const float* sWf = sm + OFF_WFC;
    const float* sWp = sm + OFF_WPR;
    const float* sBq  = sm + OFF_B;
    const float* sBf  = sm + OFF_B + 192;
    const float* sL1g = sm + OFF_B + 448, *sL1b = sm + OFF_B + 512;
    const float* sL2g = sm + OFF_B + 576, *sL2b = sm + OFF_B + 640;

    for (int it = 0; it < nloops; ++it) {
        // ============ Phase A: x += temb; LN1 -> sR(pitch65); QKV ============
        {
            const float* temb = g_TEMB + it * 64;
            float tv0 = __ldg(temb + l), tv1 = __ldg(temb + 32 + l);
            #pragma unroll
            for (int t = 0; t < 2; ++t) {
                int lt = w * 2 + t;
                float x0 = sX[lt * 65 + l]      + tv0;
                float x1 = sX[lt * 65 + 32 + l] + tv1;
                sX[lt * 65 + l]      = x0;
                sX[lt * 65 + 32 + l] = x1;
                float s1 = x0 + x1, s2 = x0 * x0 + x1 * x1;
                #pragma unroll
                for (int o = 16; o; o >>= 1) {
                    s1 += __shfl_xor_sync(0xffffffffu, s1, o);
                    s2 += __shfl_xor_sync(0xffffffffu, s2, o);
                }
                float mu = s1 * (1.0f / 64.0f);
                float rs = rsqrtf(s2 * (1.0f / 64.0f) - mu * mu + 1e-5f);
                sR[lt * 65 + l]      = (x0 - mu) * rs * sL1g[l]      + sL1b[l];
                sR[lt * 65 + 32 + l] = (x1 - mu) * rs * sL1g[32 + l] + sL1b[32 + l];
            }
        }
        __syncthreads();
        {   // QKV GEMM: warp -> 12 cols, lane -> token
            const int c0 = w * 12;
            const float* hAl = sR + l * 65;
            float acc[12];
            #pragma unroll
            for (int c = 0; c < 12; ++c) acc[c] = 0.f;
            #pragma unroll 4
            for (int k = 0; k < 64; ++k) {
                float h = hAl[k];
                float4 wa = *(const float4*)&sWq[k * 192 + c0];
                float4 wb = *(const float4*)&sWq[k * 192 + c0 + 4];
                float4 wc = *(const float4*)&sWq[k * 192 + c0 + 8];
                acc[0] += h * wa.x; acc[1] += h * wa.y; acc[2]  += h * wa.z; acc[3]  += h * wa.w;
                acc[4] += h * wb.x; acc[5] += h * wb.y; acc[6]  += h * wb.z; acc[7]  += h * wb.w;
                acc[8] += h * wc.x; acc[9] += h * wc.y; acc[10] += h * wc.z; acc[11] += h * wc.w;
            }
            const int tok = t0 + l;
            float4 o0 = make_float4(acc[0] + sBq[c0],     acc[1] + sBq[c0 + 1],
                                    acc[2] + sBq[c0 + 2], acc[3] + sBq[c0 + 3]);
            float4 o1 = make_float4(acc[4] + sBq[c0 + 4], acc[5] + sBq[c0 + 5],
                                    acc[6] + sBq[c0 + 6], acc[7] + sBq[c0 + 7]);
            float4 o2 = make_float4(acc[8] + sBq[c0 + 8], acc[9] + sBq[c0 + 9],
                                    acc[10] + sBq[c0 + 10], acc[11] + sBq[c0 + 11]);
            *(float4*)&g_QKV[tok * 192 + c0]     = o0;
            *(float4*)&g_QKV[tok * 192 + c0 + 4] = o1;
            *(float4*)&g_QKV[tok * 192 + c0 + 8] = o2;
        }
        grid_sync(++gen);

        // ============ Phase B: attention for (bb, hh) ============
        {   // stage K,V (pitch 17), float4 loads bypassing L1
            int kt = tid >> 2, ds = (tid & 3) * 4;
            float4 kv = __ldcg((const float4*)&g_QKV[(tbatt + kt) * 192 + 64  + hh * 16 + ds]);
            sR[kt * 17 + ds]     = kv.x; sR[kt * 17 + ds + 1] = kv.y;
            sR[kt * 17 + ds + 2] = kv.z; sR[kt * 17 + ds + 3] = kv.w;
            float4 vv = __ldcg((const float4*)&g_QKV[(tbatt + kt) * 192 + 128 + hh * 16 + ds]);
            sR[2176 + kt * 17 + ds]     = vv.x; sR[2176 + kt * 17 + ds + 1] = vv.y;
            sR[2176 + kt * 17 + ds + 2] = vv.z; sR[2176 + kt * 17 + ds + 3] = vv.w;
        }
        __syncthreads();
        {
            float* sP = sR + 4352 + w * 128;
            const int d = l & 15, half = l >> 4;
            const float* Vh = sR + 2176 + half * 64 * 17;
            const float* Ph = sP + half * 64;
            for (int r = 0; r < 8; ++r) {
                int qt = w * 8 + r;
                const float4* qp = (const float4*)&g_QKV[(tbatt + qt) * 192 + hh * 16];
                float4 qa = __ldcg(qp), qb = __ldcg(qp + 1);
                float4 qc = __ldcg(qp + 2), qd = __ldcg(qp + 3);
                float q[16] = {qa.x, qa.y, qa.z, qa.w, qb.x, qb.y, qb.z, qb.w,
                               qc.x, qc.y, qc.z, qc.w, qd.x, qd.y, qd.z, qd.w};
                float sc0 = 0.f, sc1 = 0.f, sc2 = 0.f, sc3 = 0.f;
                #pragma unroll
                for (int dd = 0; dd < 16; ++dd) {
                    sc0 += q[dd] * sR[l * 17 + dd];
                    sc1 += q[dd] * sR[(l + 32) * 17 + dd];
                    sc2 += q[dd] * sR[(l + 64) * 17 + dd];
                    sc3 += q[dd] * sR[(l + 96) * 17 + dd];
                }
                sc0 = sc0 * 0.25f + ((l      <= qt) ? 0.f : -1e9f);
                sc1 = sc1 * 0.25f + ((l + 32 <= qt) ? 0.f : -1e9f);
                sc2 = sc2 * 0.25f + ((l + 64 <= qt) ? 0.f : -1e9f);
                sc3 = sc3 * 0.25f + ((l + 96 <= qt) ? 0.f : -1e9f);
                float mx = fmaxf(fmaxf(sc0, sc1), fmaxf(sc2, sc3));
                #pragma unroll
                for (int o = 16; o; o >>= 1) mx = fmaxf(mx, __shfl_xor_sync(0xffffffffu, mx, o));
                float e0 = __expf(sc0 - mx), e1 = __expf(sc1 - mx);
                float e2 = __expf(sc2 - mx), e3 = __expf(sc3 - mx);
                float es = e0 + e1 + e2 + e3;
                #pragma unroll
                for (int o = 16; o; o >>= 1) es += __shfl_xor_sync(0xffffffffu, es, o);
                float inv = 1.0f / es;
                sP[l]      = e0 * inv;
                sP[l + 32] = e1 * inv;
                sP[l + 64] = e2 * inv;
                sP[l + 96] = e3 * inv;
                __syncwarp();
                // PV: half1 iterates keys at +16 offset -> bank-disjoint halves
                float ov = 0.f;
                #pragma unroll 8
                for (int k2 = 0; k2 < 64; ++k2) {
                    int kk = (k2 + half * 16) & 63;
                    ov += Ph[kk] * Vh[kk * 17 + d];
                }
                ov += __shfl_xor_sync(0xffffffffu, ov, 16);
                if (half == 0) g_A[(tbatt + qt) * 64 + hh * 16 + d] = ov;
                __syncwarp();
            }
        }
        grid_sync(++gen);

        // ============ Phase C: o-proj + LN2 + MLP (2 tokens/warp) ============
        {
            float* hW = sR + w * 640;   // h[2][64] @0, hid[2][256] @128
            int lta = 2 * w, ltb = 2 * w + 1;
            const float* Aa = g_A + (t0 + lta) * 64;
            const float* Ab = g_A + (t0 + ltb) * 64;
            float o00 = 0, o01 = 0, o10 = 0, o11 = 0;
            #pragma unroll 4
            for (int k = 0; k < 64; ++k) {
                float a0 = __ldcg(Aa + k), a1 = __ldcg(Ab + k);
                float w0 = __ldg(&wo_[k * 64 + l]), w1 = __ldg(&wo_[k * 64 + 32 + l]);
                o00 += w0 * a0; o01 += w0 * a1; o10 += w1 * a0; o11 += w1 * a1;
            }
            float xa0 = sX[lta * 65 + l]      + 0.1f * (o00 + rbo0);
            float xa1 = sX[lta * 65 + 32 + l] + 0.1f * (o10 + rbo1);
            float xb0 = sX[ltb * 65 + l]      + 0.1f * (o01 + rbo0);
            float xb1 = sX[ltb * 65 + 32 + l] + 0.1f * (o11 + rbo1);
            float s1a = xa0 + xa1, s2a = xa0 * xa0 + xa1 * xa1;
            float s1b = xb0 + xb1, s2b = xb0 * xb0 + xb1 * xb1;
            #pragma unroll
            for (int o = 16; o; o >>= 1) {
                s1a += __shfl_xor_sync(0xffffffffu, s1a, o);
                s2a += __shfl_xor_sync(0xffffffffu, s2a, o);
                s1b += __shfl_xor_sync(0xffffffffu, s1b, o);
                s2b += __shfl_xor_sync(0xffffffffu, s2b, o);
            }
            float mua = s1a * (1.f/64.f), rsa = rsqrtf(s2a * (1.f/64.f) - mua * mua + 1e-5f);
            float mub = s1b * (1.f/64.f), rsb = rsqrtf(s2b * (1.f/64.f) - mub * mub + 1e-5f);
            hW[l]      = (xa0 - mua) * rsa * sL2g[l]      + sL2b[l];
            hW[32 + l] = (xa1 - mua) * rsa * sL2g[32 + l] + sL2b[32 + l];
            hW[64 + l] = (xb0 - mub) * rsb * sL2g[l]      + sL2b[l];
            hW[96 + l] = (xb1 - mub) * rsb * sL2g[32 + l] + sL2b[32 + l];
            __syncwarp();
            float fa[8][2];
            #pragma unroll
            for (int s2 = 0; s2 < 8; ++s2) { fa[s2][0] = 0.f; fa[s2][1] = 0.f; }
            #pragma unroll 4
            for (int k = 0; k < 64; ++k) {
                float h0 = hW[k], h1v = hW[64 + k];
                #pragma unroll
                for (int s2 = 0; s2 < 8; ++s2) {
                    float wv = sWf[k * 256 + 32 * s2 + l];
                    fa[s2][0] += wv * h0; fa[s2][1] += wv * h1v;
                }
            }
            __syncwarp();
            #pragma unroll
            for (int s2 = 0; s2 < 8; ++s2) {
                #pragma unroll
                for (int t = 0; t < 2; ++t) {
                    float z = fa[s2][t] + sBf[32 * s2 + l];
                    float u = 0.7978845608028654f * (z + 0.044715f * z * z * z);
                    float e2u = __expf(2.0f * u);
                    float th = 1.0f - 2.0f / (e2u + 1.0f);
                    hW[128 + t * 256 + 32 * s2 + l] = 0.5f * z * (1.0f + th);
                }
            }
            __syncwarp();
            float p00 = 0, p01 = 0, p10 = 0, p11 = 0;
            #pragma unroll 4
            for (int k = 0; k < 256; ++k) {
                float h0 = hW[128 + k], h1v = hW[384 + k];
                float w0 = sWp[k * 64 + l], w1 = sWp[k * 64 + 32 + l];
                p00 += w0 * h0; p01 += w0 * h1v; p10 += w1 * h0; p11 += w1 * h1v;
            }
            sX[lta * 65 + l]      = xa0 + 0.1f * (p00 + rbp0);
            sX[lta * 65 + 32 + l] = xa1 + 0.1f * (p10 + rbp1);
            sX[ltb * 65 + l]      = xb0 + 0.1f * (p01 + rbp0);
            sX[ltb * 65 + 32 + l] = xb1 + 0.1f * (p11 + rbp1);
        }
        __syncthreads();   // sR must drain before next Phase A reuses it
    }

    // ================= final LN -> out =================
    {
        float g0 = __ldg(lnfg_ + l), g1 = __ldg(lnfg_ + 32 + l);
        float b0 = __ldg(lnfb_ + l), b1 = __ldg(lnfb_ + 32 + l);
        #pragma unroll
        for (int t = 0; t < 2; ++t) {
            int lt = 2 * w + t;
            float x0 = sX[lt * 65 + l], x1 = sX[lt * 65 + 32 + l];
            float s1 = x0 + x1, s2 = x0 * x0 + x1 * x1;
            #pragma unroll
            for (int o = 16; o; o >>= 1) {
                s1 += __shfl_xor_sync(0xffffffffu, s1, o);
                s2 += __shfl_xor_sync(0xffffffffu, s2, o);
            }
            float mu = s1 * (1.f/64.f);
            float rs = rsqrtf(s2 * (1.f/64.f) - mu * mu + 1e-5f);
            out[(t0 + lt) * 64 + l]      = (x0 - mu) * rs * g0 + b0;
            out[(t0 + lt) * 64 + 32 + l] = (x1 - mu) * rs * g1 + b1;
        }
    }
}

extern "C" void kernel_launch(void* const* d_in, const int* in_sizes, int n_in,
                              void* d_out, int out_size)
{
    (void)in_sizes; (void)n_in; (void)out_size;
    cudaFuncSetAttribute(lt37349035606833_kernel,
                         cudaFuncAttributeMaxDynamicSharedMemorySize, SMEM_BYTES);
    lt37349035606833_kernel<<<GRID, NTHREADS, SMEM_BYTES>>>(
        (const int*)  d_in[0],  (const int*)  d_in[1],
        (const float*)d_in[2],  (const float*)d_in[3],
        (const float*)d_in[4],  (const float*)d_in[5],
        (const float*)d_in[6],  (const float*)d_in[7],
        (const float*)d_in[8],  (const float*)d_in[9],
        (const float*)d_in[10], (const float*)d_in[11],
        (const float*)d_in[12], (const float*)d_in[13],
        (const float*)d_in[14], (const float*)d_in[15],
        (const float*)d_in[16], (const float*)d_in[17],
        (const float*)d_in[18], (const float*)d_in[19],
        (const float*)d_in[20], (const float*)d_in[21],
        (float*)d_out);
}

// round 6
// speedup vs baseline: 1.3276x; 1.2120x over previous
#include <cuda_runtime.h>

#define GRID     128
#define NTHREADS 512
#define NT       4096     // B*S tokens

// ---- device globals ----
__device__ float g_QKV[NT * 192];      // [tok][192]  (Q|K|V)
__device__ float g_A[NT * 64];         // attention output [tok][64]
__device__ float g_TEMB[4096 * 64];
__device__ unsigned g_arrive;
__device__ volatile unsigned g_release;

// ---- smem layout (floats) ----
#define OFF_WQKV 0            // [k][192]      12288
#define OFF_WFC  12288        // [k][256]      16384
#define OFF_WPR  28672        // [k(256)][64]  16384
#define OFF_B    45056        // 704: bqkv[192] bfc[256] ln1g ln1b ln2g ln2b
#define OFF_X    45760        // 32 tokens, pitch 65 = 2080
#define OFF_R    47840        // 10240 scratch
#define SMEM_FLOATS 58080
#define SMEM_BYTES (SMEM_FLOATS * 4)   // 232320 <= 232448

// ---- packed f32x2 helpers (FFMA2 is PTX-only) ----
__device__ __forceinline__ unsigned long long bcast2(float x) {
    unsigned long long r; asm("mov.b64 %0,{%1,%1};" : "=l"(r) : "f"(x)); return r;
}
__device__ __forceinline__ void upk2(unsigned long long v, float& x, float& y) {
    asm("mov.b64 {%0,%1},%2;" : "=f"(x), "=f"(y) : "l"(v));
}
__device__ __forceinline__ void fma2(unsigned long long& d, unsigned long long a,
                                     unsigned long long b) {
    asm("fma.rn.f32x2 %0,%1,%2,%0;" : "+l"(d) : "l"(a), "l"(b));
}

__device__ __forceinline__ void grid_sync(unsigned gen) {
    __syncthreads();
    if (threadIdx.x == 0) {
        __threadfence();
        unsigned prev = atomicAdd(&g_arrive, 1u);
        if (prev == gen * GRID - 1u) {
            __threadfence();
            g_release = gen;
        } else {
            while (*(volatile unsigned*)&g_release < gen) { __nanosleep(32); }
        }
        __threadfence();
    }
    __syncthreads();
}

extern "C" __global__ void __launch_bounds__(NTHREADS, 1)
lt37349035606833_kernel(
    const int*   __restrict__ idx,   const int*   __restrict__ nloops_p,
    const float* __restrict__ wte,   const float* __restrict__ wpe,
    const float* __restrict__ tw1,   const float* __restrict__ tb1,
    const float* __restrict__ tw2,   const float* __restrict__ tb2,
    const float* __restrict__ ln1g_, const float* __restrict__ ln1b_,
    const float* __restrict__ wqkv_, const float* __restrict__ bqkv_,
    const float* __restrict__ wo_,   const float* __restrict__ bo_,
    const float* __restrict__ ln2g_, const float* __restrict__ ln2b_,
    const float* __restrict__ wfc_,  const float* __restrict__ bfc_,
    const float* __restrict__ wpr_,  const float* __restrict__ bpr_,
    const float* __restrict__ lnfg_, const float* __restrict__ lnfb_,
    float* __restrict__ out)
{
    extern __shared__ float sm[];
    const int tid = threadIdx.x;
    const int blk = blockIdx.x;
    const int w = tid >> 5, l = tid & 31;
    const int nloops = *nloops_p;
    unsigned gen = g_release;

    // ---- stage weights/biases ----
    for (int i = tid; i < 12288; i += NTHREADS) sm[OFF_WQKV + i] = wqkv_[i];
    for (int i = tid; i < 16384; i += NTHREADS) {
        sm[OFF_WFC + i] = wfc_[i];
        sm[OFF_WPR + i] = wpr_[i];
    }
    if (tid < 192)                sm[OFF_B + tid] = bqkv_[tid];
    if (tid >= 192 && tid < 448)  sm[OFF_B + tid] = bfc_[tid - 192];
    if (tid < 64) {
        sm[OFF_B + 448 + tid] = ln1g_[tid];
        sm[OFF_B + 512 + tid] = ln1b_[tid];
        sm[OFF_B + 576 + tid] = ln2g_[tid];
        sm[OFF_B + 640 + tid] = ln2b_[tid];
    }

    // ---- initial x tile (pitch 65) ----
    const int t0 = blk * 32;
    for (int i = tid; i < 2048; i += NTHREADS) {
        int t = i >> 6, d = i & 63;
        int tok = t0 + t;
        sm[OFF_X + t * 65 + d] = wte[idx[tok] * 64 + d] + wpe[(tok & 127) * 64 + d];
    }
    __syncthreads();

    // ---- precompute temb for all steps ----
    float* sR = sm + OFF_R;
    for (int s = blk; s < nloops; s += GRID) {
        float tt = (float)s;
        if (tid < 128) {
            float f = __expf(-9.2103403719761836f * (float)tid / 128.0f);
            float a = tt * f;
            sR[tid]       = cosf(a);
            sR[128 + tid] = sinf(a);
        }
        __syncthreads();
        for (int j = tid; j < 1024; j += NTHREADS) {
            float z = tb1[j];
            for (int k = 0; k < 256; ++k) z += sR[k] * tw1[k * 1024 + j];
            sR[256 + j] = z / (1.0f + __expf(-z));
        }
        __syncthreads();
        if (tid < 64) {
            float z = tb2[tid];
            for (int k = 0; k < 1024; ++k) z += sR[256 + k] * tw2[k * 64 + tid];
            g_TEMB[s * 64 + tid] = z;
        }
        __syncthreads();
    }
    grid_sync(++gen);

    const int bb = blk >> 2, hh = blk & 3;
    const int tbatt = bb * 128;
    float* sX  = sm + OFF_X;
    const float* sWq = sm + OFF_WQKV;
    const float* sWf = sm + OFF_WFC;
    const float* sWp = sm + OFF_WPR;
    const float* sBq  = sm + OFF_B;
    const float* sBf  = sm + OFF_B + 192;
    const float* sL1g = sm + OFF_B + 448, *sL1b = sm + OFF_B + 512;
    const float* sL2g = sm + OFF_B + 576, *sL2b = sm + OFF_B + 640;

    for (int it = 0; it < nloops; ++it) {
        // ============ Phase A: x += temb; LN1 -> sR(pitch65); QKV ============
        {
            const float* temb = g_TEMB + it * 64;
            float tv0 = __ldg(temb + l), tv1 = __ldg(temb + 32 + l);
            #pragma unroll
            for (int t = 0; t < 2; ++t) {
                int lt = w * 2 + t;
                float x0 = sX[lt * 65 + l]      + tv0;
                float x1 = sX[lt * 65 + 32 + l] + tv1;
                sX[lt * 65 + l]      = x0;
                sX[lt * 65 + 32 + l] = x1;
                float s1 = x0 + x1, s2 = x0 * x0 + x1 * x1;
                #pragma unroll
                for (int o = 16; o; o >>= 1) {
                    s1 += __shfl_xor_sync(0xffffffffu, s1, o);
                    s2 += __shfl_xor_sync(0xffffffffu, s2, o);
                }
                float mu = s1 * (1.0f / 64.0f);
                float rs = rsqrtf(s2 * (1.0f / 64.0f) - mu * mu + 1e-5f);
                sR[lt * 65 + l]      = (x0 - mu) * rs * sL1g[l]      + sL1b[l];
                sR[lt * 65 + 32 + l] = (x1 - mu) * rs * sL1g[32 + l] + sL1b[32 + l];
            }
        }
        __syncthreads();
        {   // QKV GEMM: warp -> 12 cols, lane -> token, f32x2
            const int c0 = w * 12;
            const float* hAl = sR + l * 65;
            unsigned long long acc[6] = {0, 0, 0, 0, 0, 0};
            #pragma unroll 4
            for (int k = 0; k < 64; ++k) {
                unsigned long long h2 = bcast2(hAl[k]);
                const float* wr = sWq + k * 192 + c0;
                ulonglong2 wa = *(const ulonglong2*)(wr);
                ulonglong2 wb = *(const ulonglong2*)(wr + 4);
                ulonglong2 wc = *(const ulonglong2*)(wr + 8);
                fma2(acc[0], h2, wa.x); fma2(acc[1], h2, wa.y);
                fma2(acc[2], h2, wb.x); fma2(acc[3], h2, wb.y);
                fma2(acc[4], h2, wc.x); fma2(acc[5], h2, wc.y);
            }
            float c[12];
            #pragma unroll
            for (int j = 0; j < 6; ++j) upk2(acc[j], c[2 * j], c[2 * j + 1]);
            const int tok = t0 + l;
            float4 o0 = make_float4(c[0] + sBq[c0],     c[1] + sBq[c0 + 1],
                                    c[2] + sBq[c0 + 2], c[3] + sBq[c0 + 3]);
            float4 o1 = make_float4(c[4] + sBq[c0 + 4], c[5] + sBq[c0 + 5],
                                    c[6] + sBq[c0 + 6], c[7] + sBq[c0 + 7]);
            float4 o2 = make_float4(c[8] + sBq[c0 + 8],  c[9] + sBq[c0 + 9],
                                    c[10] + sBq[c0 + 10], c[11] + sBq[c0 + 11]);
            *(float4*)&g_QKV[tok * 192 + c0]     = o0;
            *(float4*)&g_QKV[tok * 192 + c0 + 4] = o1;
            *(float4*)&g_QKV[tok * 192 + c0 + 8] = o2;
        }
        grid_sync(++gen);

        // ============ Phase B: attention for (bb, hh), causal-skipped ============
        {   // stage K,V (pitch 17)
            int kt = tid >> 2, ds = (tid & 3) * 4;
            float4 kv = __ldcg((const float4*)&g_QKV[(tbatt + kt) * 192 + 64  + hh * 16 + ds]);
            sR[kt * 17 + ds]     = kv.x; sR[kt * 17 + ds + 1] = kv.y;
            sR[kt * 17 + ds + 2] = kv.z; sR[kt * 17 + ds + 3] = kv.w;
            float4 vv = __ldcg((const float4*)&g_QKV[(tbatt + kt) * 192 + 128 + hh * 16 + ds]);
            sR[2176 + kt * 17 + ds]     = vv.x; sR[2176 + kt * 17 + ds + 1] = vv.y;
            sR[2176 + kt * 17 + ds + 2] = vv.z; sR[2176 + kt * 17 + ds + 3] = vv.w;
        }
        __syncthreads();
        {
            const float* sK = sR;
            const float* sV = sR + 2176;
            float* sP = sR + 4352 + w * 128;
            const int d = l & 15, half = l >> 4;
            #pragma unroll 1
            for (int r = 0; r < 8; ++r) {
                const int qt = w + 16 * r;          // interleaved -> warp balance
                const int gq = qt >> 5;             // highest active key-group
                const float4* qp = (const float4*)&g_QKV[(tbatt + qt) * 192 + hh * 16];
                float4 qa = __ldcg(qp),     qb = __ldcg(qp + 1);
                float4 qc = __ldcg(qp + 2), qd = __ldcg(qp + 3);
                float q[16] = {qa.x, qa.y, qa.z, qa.w, qb.x, qb.y, qb.z, qb.w,
                               qc.x, qc.y, qc.z, qc.w, qd.x, qd.y, qd.z, qd.w};
                float e[4];
                float mx = -1e30f;
                #pragma unroll
                for (int g = 0; g < 4; ++g) {
                    if (g > gq) break;              // uniform per warp
                    const float* Kr = sK + (32 * g + l) * 17;
                    float s = 0.f;
                    #pragma unroll
                    for (int dd = 0; dd < 16; ++dd) s += q[dd] * Kr[dd];
                    s = s * 0.25f + ((32 * g + l <= qt) ? 0.f : -1e9f);
                    e[g] = s;
                    mx = fmaxf(mx, s);
                }
                #pragma unroll
                for (int o = 16; o; o >>= 1) mx = fmaxf(mx, __shfl_xor_sync(0xffffffffu, mx, o));
                float es = 0.f;
                #pragma unroll
                for (int g = 0; g < 4; ++g) {
                    if (g > gq) break;
                    e[g] = __expf(e[g] - mx);
                    es += e[g];
                }
                #pragma unroll
                for (int o = 16; o; o >>= 1) es += __shfl_xor_sync(0xffffffffu, es, o);
                float inv = 1.0f / es;
                #pragma unroll
                for (int g = 0; g < 4; ++g) {
                    if (g > gq) break;
                    sP[32 * g + l] = e[g] * inv;
                }
                __syncwarp();
                // PV: halves take groups of their parity; 16/16 rotated inner
                float ov = 0.f;
                #pragma unroll
                for (int i = 0; i < 2; ++i) {
                    int g = half + 2 * i;
                    if (g <= gq) {                  // branch skip: no stale reads
                        const float* Pg = sP + 32 * g;
                        const float* Vg = sV + (32 * g) * 17 + d;
                        const float* P1 = Pg + 16 * half;
                        const float* V1 = Vg + (16 * half) * 17;
                        const float* P2 = Pg + 16 - 16 * half;
                        const float* V2 = Vg + (16 - 16 * half) * 17;
                        float pv = 0.f;
                        #pragma unroll
                        for (int k2 = 0; k2 < 16; ++k2) pv += P1[k2] * V1[k2 * 17];
                        #pragma unroll
                        for (int k2 = 0; k2 < 16; ++k2) pv += P2[k2] * V2[k2 * 17];
                        ov += pv;
                    }
                }
                ov += __shfl_xor_sync(0xffffffffu, ov, 16);
                if (half == 0) g_A[(tbatt + qt) * 64 + hh * 16 + d] = ov;
                __syncwarp();
            }
        }
        grid_sync(++gen);

        // ============ Phase C: o-proj + LN2 + MLP (lane = token) ============
        {   // stage A tile -> sR[0..2080) pitch 65
            int t = tid >> 4, ds = (tid & 15) * 4;
            float4 av = __ldcg((const float4*)&g_A[(t0 + t) * 64 + ds]);
            sR[t * 65 + ds]     = av.x; sR[t * 65 + ds + 1] = av.y;
            sR[t * 65 + ds + 2] = av.z; sR[t * 65 + ds + 3] = av.w;
        }
        __syncthreads();
        {   // o-proj: warp -> 4 cols, lane -> token; w_o via L1-broadcast LDG
            const int c0o = w * 4;
            unsigned long long oac[2] = {0, 0};
            const float* sA = sR + l * 65;
            #pragma unroll 4
            for (int k = 0; k < 64; ++k) {
                unsigned long long a2 = bcast2(sA[k]);
                ulonglong2 wv = __ldg((const ulonglong2*)&wo_[k * 64 + c0o]);
                fma2(oac[0], a2, wv.x); fma2(oac[1], a2, wv.y);
            }
            float o4[4];
            upk2(oac[0], o4[0], o4[1]); upk2(oac[1], o4[2], o4[3]);
            float4 bo4 = __ldg((const float4*)(bo_ + c0o));
            float* xr = sX + l * 65 + c0o;
            xr[0] += 0.1f * (o4[0] + bo4.x);
            xr[1] += 0.1f * (o4[1] + bo4.y);
            xr[2] += 0.1f * (o4[2] + bo4.z);
            xr[3] += 0.1f * (o4[3] + bo4.w);
        }
        __syncthreads();
        {   // LN2: 2 tokens/warp (lane = dim) -> h in sR[0..2080)
            #pragma unroll
            for (int t = 0; t < 2; ++t) {
                int lt = 2 * w + t;
                float x0 = sX[lt * 65 + l], x1 = sX[lt * 65 + 32 + l];
                float s1 = x0 + x1, s2 = x0 * x0 + x1 * x1;
                #pragma unroll
                for (int o = 16; o; o >>= 1) {
                    s1 += __shfl_xor_sync(0xffffffffu, s1, o);
                    s2 += __shfl_xor_sync(0xffffffffu, s2, o);
                }
                float mu = s1 * (1.f / 64.f);
                float rs = rsqrtf(s2 * (1.f / 64.f) - mu * mu + 1e-5f);
                sR[lt * 65 + l]      = (x0 - mu) * rs * sL2g[l]      + sL2b[l];
                sR[lt * 65 + 32 + l] = (x1 - mu) * rs * sL2g[32 + l] + sL2b[32 + l];
            }
        }
        __syncthreads();
        float gl[16];
        {   // FC: warp -> 16 cols, lane -> token; gelu in regs
            const int c0f = w * 16;
            unsigned long long fac[8] = {0, 0, 0, 0, 0, 0, 0, 0};
            const float* sH = sR + l * 65;
            #pragma unroll 2
            for (int k = 0; k < 64; ++k) {
                unsigned long long h2 = bcast2(sH[k]);
                const float* wr = sWf + k * 256 + c0f;
                ulonglong2 wa = *(const ulonglong2*)(wr);
                ulonglong2 wb = *(const ulonglong2*)(wr + 4);
                ulonglong2 wc = *(const ulonglong2*)(wr + 8);
                ulonglong2 wd = *(const ulonglong2*)(wr + 12);
                fma2(fac[0], h2, wa.x); fma2(fac[1], h2, wa.y);
                fma2(fac[2], h2, wb.x); fma2(fac[3], h2, wb.y);
                fma2(fac[4], h2, wc.x); fma2(fac[5], h2, wc.y);
                fma2(fac[6], h2, wd.x); fma2(fac[7], h2, wd.y);
            }
            float f[16];
            #pragma unroll
            for (int j = 0; j < 8; ++j) upk2(fac[j], f[2 * j], f[2 * j + 1]);
            #pragma unroll
            for (int j = 0; j < 16; ++j) {
                float z = f[j] + sBf[c0f + j];
                float u = 0.7978845608028654f * (z + 0.044715f * z * z * z);
                float e2u = __expf(2.0f * u);
                float th = 1.0f - 2.0f / (e2u + 1.0f);
                gl[j] = 0.5f * z * (1.0f + th);
            }
        }
        __syncthreads();   // all h reads done; hid overlaps h region
        {   // store hid at pitch 257 (>=256 elems/row, odd): sR[0..8223)
            const int c0f = w * 16;
            float* hr = sR + l * 257 + c0f;
            #pragma unroll
            for (int j = 0; j < 16; ++j) hr[j] = gl[j];
        }
        __syncthreads();
        {   // PR: warp -> 4 cols, lane -> token; residual into sX
            const int c0p = w * 4;
            unsigned long long pac[2] = {0, 0};
            const float* sHd = sR + l * 257;
            #pragma unroll 8
            for (int k = 0; k < 256; ++k) {
                unsigned long long h2 = bcast2(sHd[k]);
                ulonglong2 wv = *(const ulonglong2*)&sWp[k * 64 + c0p];
                fma2(pac[0], h2, wv.x); fma2(pac[1], h2, wv.y);
            }
            float p4[4];
            upk2(pac[0], p4[0], p4[1]); upk2(pac[1], p4[2], p4[3]);
            float4 bp4 = __ldg((const float4*)(bpr_ + c0p));
            float* xr = sX + l * 65 + c0p;
            xr[0] += 0.1f * (p4[0] + bp4.x);
            xr[1] += 0.1f * (p4[1] + bp4.y);
            xr[2] += 0.1f * (p4[2] + bp4.z);
            xr[3] += 0.1f * (p4[3] + bp4.w);
        }
        __syncthreads();
    }

    // ================= final LN -> out =================
    {
        float g0 = __ldg(lnfg_ + l), g1 = __ldg(lnfg_ + 32 + l);
        float b0 = __ldg(lnfb_ + l), b1 = __ldg(lnfb_ + 32 + l);
        #pragma unroll
        for (int t = 0; t < 2; ++t) {
            int lt = 2 * w + t;
            float x0 = sX[lt * 65 + l], x1 = sX[lt * 65 + 32 + l];
            float s1 = x0 + x1, s2 = x0 * x0 + x1 * x1;
            #pragma unroll
            for (int o = 16; o; o >>= 1) {
                s1 += __shfl_xor_sync(0xffffffffu, s1, o);
                s2 += __shfl_xor_sync(0xffffffffu, s2, o);
            }
            float mu = s1 * (1.f / 64.f);
            float rs = rsqrtf(s2 * (1.f / 64.f) - mu * mu + 1e-5f);
            out[(t0 + lt) * 64 + l]      = (x0 - mu) * rs * g0 + b0;
            out[(t0 + lt) * 64 + 32 + l] = (x1 - mu) * rs * g1 + b1;
        }
    }
}

extern "C" void kernel_launch(void* const* d_in, const int* in_sizes, int n_in,
                              void* d_out, int out_size)
{
    (void)in_sizes; (void)n_in; (void)out_size;
    cudaFuncSetAttribute(lt37349035606833_kernel,
                         cudaFuncAttributeMaxDynamicSharedMemorySize, SMEM_BYTES);
    lt37349035606833_kernel<<<GRID, NTHREADS, SMEM_BYTES>>>(
        (const int*)  d_in[0],  (const int*)  d_in[1],
        (const float*)d_in[2],  (const float*)d_in[3],
        (const float*)d_in[4],  (const float*)d_in[5],
        (const float*)d_in[6],  (const float*)d_in[7],
        (const float*)d_in[8],  (const float*)d_in[9],
        (const float*)d_in[10], (const float*)d_in[11],
        (const float*)d_in[12], (const float*)d_in[13],
        (const float*)d_in[14], (const float*)d_in[15],
        (const float*)d_in[16], (const float*)d_in[17],
        (const float*)d_in[18], (const float*)d_in[19],
        (const float*)d_in[20], (const float*)d_in[21],
        (float*)d_out);
}

// round 8
// speedup vs baseline: 1.3378x; 1.0077x over previous
#include <cuda_runtime.h>
#include <cstdint>

#define GRID     128
#define NTHREADS 512
#define NT       4096     // B*S tokens

// ---- device globals ----
__device__ float g_Q[NT * 64];          // Q per token
__device__ float g_HID[GRID * 8192];    // per-block MLP hidden, [k][tok] k-major
__device__ float g_TEMB[4096 * 64];
__device__ unsigned g_arrive;
__device__ volatile unsigned g_release;

// ---- smem layout (floats) ----
#define OFF_WQKV 0            // [k][192]      12288
#define OFF_WFC  12288        // [k][256]      16384
#define OFF_WPR  28672        // [k(256)][64]  16384
#define OFF_B    45056        // 704
#define OFF_X    45760        // 32 tokens pitch 65 = 2080
#define OFF_K    47840        // K[128] pitch 17 = 2176 (peer-pushed)
#define OFF_V    50016        // V[128] pitch 17 = 2176 (peer-pushed)
#define OFF_HA   52192        // h (LN out) / A landing zone, 32x65 = 2080
#define OFF_P    54272        // softmax P, 16 warps x 128 = 2048
#define SMEM_FLOATS 56320
#define SMEM_BYTES (SMEM_FLOATS * 4)   // 225280 <= 232448

// ---- packed f32x2 helpers ----
__device__ __forceinline__ unsigned long long bcast2(float x) {
    unsigned long long r; asm("mov.b64 %0,{%1,%1};" : "=l"(r) : "f"(x)); return r;
}
__device__ __forceinline__ void upk2(unsigned long long v, float& x, float& y) {
    asm("mov.b64 {%0,%1},%2;" : "=f"(x), "=f"(y) : "l"(v));
}
__device__ __forceinline__ void fma2(unsigned long long& d, unsigned long long a,
                                     unsigned long long b) {
    asm("fma.rn.f32x2 %0,%1,%2,%0;" : "+l"(d) : "l"(a), "l"(b));
}

// ---- cluster helpers ----
__device__ __forceinline__ uint32_t smem_u32(const void* p) {
    uint32_t a;
    asm("{ .reg .u64 t; cvta.to.shared.u64 t, %1; cvt.u32.u64 %0, t; }" : "=r"(a) : "l"(p));
    return a;
}
__device__ __forceinline__ void sts_cluster1(uint32_t laddr, int rank, float v) {
    uint32_t r;
    asm volatile("mapa.shared::cluster.u32 %0, %1, %2;" : "=r"(r) : "r"(laddr), "r"(rank));
    asm volatile("st.shared::cluster.f32 [%0], %1;" :: "r"(r), "f"(v) : "memory");
}
#define CLUSTER_BAR() do { \
    asm volatile("barrier.cluster.arrive.aligned;" ::: "memory"); \
    asm volatile("barrier.cluster.wait.aligned;"   ::: "memory"); \
} while (0)

__device__ __forceinline__ void grid_sync(unsigned gen) {
    __syncthreads();
    if (threadIdx.x == 0) {
        __threadfence();
        unsigned prev = atomicAdd(&g_arrive, 1u);
        if (prev == gen * GRID - 1u) {
            __threadfence();
            g_release = gen;
        } else {
            while (*(volatile unsigned*)&g_release < gen) { __nanosleep(32); }
        }
        __threadfence();
    }
    __syncthreads();
}

extern "C" __global__ void __launch_bounds__(NTHREADS, 1) __cluster_dims__(4, 1, 1)
lt37349035606833_kernel(
    const int*   __restrict__ idx,   const int*   __restrict__ nloops_p,
    const float* __restrict__ wte,   const float* __restrict__ wpe,
    const float* __restrict__ tw1,   const float* __restrict__ tb1,
    const float* __restrict__ tw2,   const float* __restrict__ tb2,
    const float* __restrict__ ln1g_, const float* __restrict__ ln1b_,
    const float* __restrict__ wqkv_, const float* __restrict__ bqkv_,
    const float* __restrict__ wo_,   const float* __restrict__ bo_,
    const float* __restrict__ ln2g_, const float* __restrict__ ln2b_,
    const float* __restrict__ wfc_,  const float* __restrict__ bfc_,
    const float* __restrict__ wpr_,  const float* __restrict__ bpr_,
    const float* __restrict__ lnfg_, const float* __restrict__ lnfb_,
    float* __restrict__ out)
{
    extern __shared__ float sm[];
    const int tid = threadIdx.x;
    const int blk = blockIdx.x;
    const int w = tid >> 5, l = tid & 31;
    const int nloops = *nloops_p;
    unsigned gen = g_release;
    const uint32_t smb = smem_u32(sm);

    // ---- stage weights/biases ----
    for (int i = tid; i < 12288; i += NTHREADS) sm[OFF_WQKV + i] = wqkv_[i];
    for (int i = tid; i < 16384; i += NTHREADS) {
        sm[OFF_WFC + i] = wfc_[i];
        sm[OFF_WPR + i] = wpr_[i];
    }
    if (tid < 192)                sm[OFF_B + tid] = bqkv_[tid];
    if (tid >= 192 && tid < 448)  sm[OFF_B + tid] = bfc_[tid - 192];
    if (tid < 64) {
        sm[OFF_B + 448 + tid] = ln1g_[tid];
        sm[OFF_B + 512 + tid] = ln1b_[tid];
        sm[OFF_B + 576 + tid] = ln2g_[tid];
        sm[OFF_B + 640 + tid] = ln2b_[tid];
    }

    // ---- initial x tile (pitch 65) ----
    const int t0 = blk * 32;
    for (int i = tid; i < 2048; i += NTHREADS) {
        int t = i >> 6, d = i & 63;
        int tok = t0 + t;
        sm[OFF_X + t * 65 + d] = wte[idx[tok] * 64 + d] + wpe[(tok & 127) * 64 + d];
    }
    __syncthreads();

    // ---- precompute temb (scratch in K/V region; safe: grid_sync below) ----
    {
        float* sT = sm + OFF_K;
        for (int s = blk; s < nloops; s += GRID) {
            float tt = (float)s;
            if (tid < 128) {
                float f = __expf(-9.2103403719761836f * (float)tid / 128.0f);
                float a = tt * f;
                sT[tid]       = cosf(a);
                sT[128 + tid] = sinf(a);
            }
            __syncthreads();
            for (int j = tid; j < 1024; j += NTHREADS) {
                float z = tb1[j];
                for (int k = 0; k < 256; ++k) z += sT[k] * tw1[k * 1024 + j];
                sT[256 + j] = z / (1.0f + __expf(-z));
            }
            __syncthreads();
            if (tid < 64) {
                float z = tb2[tid];
                for (int k = 0; k < 1024; ++k) z += sT[256 + k] * tw2[k * 64 + tid];
                g_TEMB[s * 64 + tid] = z;
            }
            __syncthreads();
        }
    }
    grid_sync(++gen);

    const int bb = blk >> 2, rc = blk & 3;   // cluster rank == head index
    const int tbatt = bb * 128;
    float* sX  = sm + OFF_X;
    float* sHA = sm + OFF_HA;                // h / A landing zone
    const float* sK = sm + OFF_K;
    const float* sV = sm + OFF_V;
    const float* sWq = sm + OFF_WQKV;
    const float* sWf = sm + OFF_WFC;
    const float* sWp = sm + OFF_WPR;
    const float* sBq  = sm + OFF_B;
    const float* sBf  = sm + OFF_B + 192;
    const float* sL1g = sm + OFF_B + 448, *sL1b = sm + OFF_B + 512;
    const float* sL2g = sm + OFF_B + 576, *sL2b = sm + OFF_B + 640;

    for (int it = 0; it < nloops; ++it) {
        // ============ Phase A: x += temb; LN1 -> sHA; QKV + push ============
        {
            const float* temb = g_TEMB + it * 64;
            float tv0 = __ldg(temb + l), tv1 = __ldg(temb + 32 + l);
            #pragma unroll
            for (int t = 0; t < 2; ++t) {
                int lt = w * 2 + t;
                float x0 = sX[lt * 65 + l]      + tv0;
                float x1 = sX[lt * 65 + 32 + l] + tv1;
                sX[lt * 65 + l]      = x0;
                sX[lt * 65 + 32 + l] = x1;
                float s1 = x0 + x1, s2 = x0 * x0 + x1 * x1;
                #pragma unroll
                for (int o = 16; o; o >>= 1) {
                    s1 += __shfl_xor_sync(0xffffffffu, s1, o);
                    s2 += __shfl_xor_sync(0xffffffffu, s2, o);
                }
                float mu = s1 * (1.0f / 64.0f);
                float rs = rsqrtf(s2 * (1.0f / 64.0f) - mu * mu + 1e-5f);
                sHA[lt * 65 + l]      = (x0 - mu) * rs * sL1g[l]      + sL1b[l];
                sHA[lt * 65 + 32 + l] = (x1 - mu) * rs * sL1g[32 + l] + sL1b[32 + l];
            }
        }
        __syncthreads();
        {   // QKV GEMM: warp -> 12 cols, lane -> token; push K/V via DSMEM (scalar)
            const int c0 = w * 12;
            const float* hAl = sHA + l * 65;
            unsigned long long acc[6] = {0, 0, 0, 0, 0, 0};
            #pragma unroll 4
            for (int k = 0; k < 64; ++k) {
                unsigned long long h2 = bcast2(hAl[k]);
                const float* wr = sWq + k * 192 + c0;
                ulonglong2 wa = *(const ulonglong2*)(wr);
                ulonglong2 wb = *(const ulonglong2*)(wr + 4);
                ulonglong2 wc = *(const ulonglong2*)(wr + 8);
                fma2(acc[0], h2, wa.x); fma2(acc[1], h2, wa.y);
                fma2(acc[2], h2, wb.x); fma2(acc[3], h2, wb.y);
                fma2(acc[4], h2, wc.x); fma2(acc[5], h2, wc.y);
            }
            float c[12];
            #pragma unroll
            for (int j = 0; j < 6; ++j) upk2(acc[j], c[2 * j], c[2 * j + 1]);
            const int tok = t0 + l;          // global token
            const int tkb = rc * 32 + l;     // token within batch (0..127)
            #pragma unroll
            for (int g3 = 0; g3 < 3; ++g3) {
                int cg = c0 + 4 * g3;
                float v0 = c[4*g3]   + sBq[cg];
                float v1 = c[4*g3+1] + sBq[cg+1];
                float v2 = c[4*g3+2] + sBq[cg+2];
                float v3 = c[4*g3+3] + sBq[cg+3];
                if (cg < 64) {
                    *(float4*)&g_Q[tok * 64 + cg] = make_float4(v0, v1, v2, v3);
                } else if (cg < 128) {
                    int tr = (cg - 64) >> 4, d4 = (cg - 64) & 15;
                    uint32_t a = smb + (OFF_K + tkb * 17 + d4) * 4;
                    sts_cluster1(a,      tr, v0);
                    sts_cluster1(a + 4,  tr, v1);
                    sts_cluster1(a + 8,  tr, v2);
                    sts_cluster1(a + 12, tr, v3);
                } else {
                    int tr = (cg - 128) >> 4, d4 = (cg - 128) & 15;
                    uint32_t a = smb + (OFF_V + tkb * 17 + d4) * 4;
                    sts_cluster1(a,      tr, v0);
                    sts_cluster1(a + 4,  tr, v1);
                    sts_cluster1(a + 8,  tr, v2);
                    sts_cluster1(a + 12, tr, v3);
                }
            }
        }
        CLUSTER_BAR();   // bar1: QKV delivered everywhere

        // ============ Phase B: attention for (bb, rc); K/V already local ============
        {
            float* sP = sm + OFF_P + w * 128;
            const int d = l & 15, half = l >> 4;
            #pragma unroll 1
            for (int r = 0; r < 8; ++r) {
                const int qt = w + 16 * r;          // interleaved -> warp balance
                const int gq = qt >> 5;
                const float4* qp = (const float4*)&g_Q[(tbatt + qt) * 64 + rc * 16];
                float4 qa = __ldcg(qp),     qb = __ldcg(qp + 1);
                float4 qc = __ldcg(qp + 2), qd = __ldcg(qp + 3);
                float q[16] = {qa.x, qa.y, qa.z, qa.w, qb.x, qb.y, qb.z, qb.w,
                               qc.x, qc.y, qc.z, qc.w, qd.x, qd.y, qd.z, qd.w};
                float e[4];
                float mx = -1e30f;
                #pragma unroll
                for (int g = 0; g < 4; ++g) {
                    if (g > gq) break;
                    const float* Kr = sK + (32 * g + l) * 17;
                    float s = 0.f;
                    #pragma unroll
                    for (int dd = 0; dd < 16; ++dd) s += q[dd] * Kr[dd];
                    s = s * 0.25f + ((32 * g + l <= qt) ? 0.f : -1e9f);
                    e[g] = s;
                    mx = fmaxf(mx, s);
                }
                #pragma unroll
                for (int o = 16; o; o >>= 1) mx = fmaxf(mx, __shfl_xor_sync(0xffffffffu, mx, o));
                float es = 0.f;
                #pragma unroll
                for (int g = 0; g < 4; ++g) {
                    if (g > gq) break;
                    e[g] = __expf(e[g] - mx);
                    es += e[g];
                }
                #pragma unroll
                for (int o = 16; o; o >>= 1) es += __shfl_xor_sync(0xffffffffu, es, o);
                float inv = 1.0f / es;
                #pragma unroll
                for (int g = 0; g < 4; ++g) {
                    if (g > gq) break;
                    sP[32 * g + l] = e[g] * inv;
                }
                __syncwarp();
                float ov = 0.f;
                #pragma unroll
                for (int i = 0; i < 2; ++i) {
                    int g = half + 2 * i;
                    if (g <= gq) {
                        const float* Pg = sP + 32 * g;
                        const float* Vg = sV + (32 * g) * 17 + d;
                        const float* P1 = Pg + 16 * half;
                        const float* V1 = Vg + (16 * half) * 17;
                        const float* P2 = Pg + 16 - 16 * half;
                        const float* V2 = Vg + (16 - 16 * half) * 17;
                        float pv = 0.f;
                        #pragma unroll
                        for (int k2 = 0; k2 < 16; ++k2) pv += P1[k2] * V1[k2 * 17];
                        #pragma unroll
                        for (int k2 = 0; k2 < 16; ++k2) pv += P2[k2] * V2[k2 * 17];
                        ov += pv;
                    }
                }
                ov += __shfl_xor_sync(0xffffffffu, ov, 16);
                if (half == 0) {   // push A to token-owner CTA's sHA
                    sts_cluster1(smb + (OFF_HA + (qt & 31) * 65 + rc * 16 + d) * 4,
                                 qt >> 5, ov);
                }
                __syncwarp();
            }
        }
        CLUSTER_BAR();   // bar2: A delivered everywhere

        // ============ Phase C: o-proj + LN2 + MLP (lane = token) ============
        {   // o-proj: warp -> 4 cols, lane -> token; A already in sHA
            const int c0o = w * 4;
            unsigned long long oac[2] = {0, 0};
            const float* sA = sHA + l * 65;
            #pragma unroll 4
            for (int k = 0; k < 64; ++k) {
                unsigned long long a2 = bcast2(sA[k]);
                ulonglong2 wv = __ldg((const ulonglong2*)&wo_[k * 64 + c0o]);
                fma2(oac[0], a2, wv.x); fma2(oac[1], a2, wv.y);
            }
            float o4[4];
            upk2(oac[0], o4[0], o4[1]); upk2(oac[1], o4[2], o4[3]);
            float4 bo4 = __ldg((const float4*)(bo_ + c0o));
            float* xr = sX + l * 65 + c0o;
            xr[0] += 0.1f * (o4[0] + bo4.x);
            xr[1] += 0.1f * (o4[1] + bo4.y);
            xr[2] += 0.1f * (o4[2] + bo4.z);
            xr[3] += 0.1f * (o4[3] + bo4.w);
        }
        __syncthreads();
        {   // LN2: 2 tokens/warp -> h in sHA (A fully consumed)
            #pragma unroll
            for (int t = 0; t < 2; ++t) {
                int lt = 2 * w + t;
                float x0 = sX[lt * 65 + l], x1 = sX[lt * 65 + 32 + l];
                float s1 = x0 + x1, s2 = x0 * x0 + x1 * x1;
                #pragma unroll
                for (int o = 16; o; o >>= 1) {
                    s1 += __shfl_xor_sync(0xffffffffu, s1, o);
                    s2 += __shfl_xor_sync(0xffffffffu, s2, o);
                }
                float mu = s1 * (1.f / 64.f);
                float rs = rsqrtf(s2 * (1.f / 64.f) - mu * mu + 1e-5f);
                sHA[lt * 65 + l]      = (x0 - mu) * rs * sL2g[l]      + sL2b[l];
                sHA[lt * 65 + 32 + l] = (x1 - mu) * rs * sL2g[32 + l] + sL2b[32 + l];
            }
        }
        __syncthreads();
        {   // FC: warp -> 16 cols, lane -> token; gelu; hid -> gmem [k][tok]
            const int c0f = w * 16;
            unsigned long long fac[8] = {0, 0, 0, 0, 0, 0, 0, 0};
            const float* sH = sHA + l * 65;
            #pragma unroll 2
            for (int k = 0; k < 64; ++k) {
                unsigned long long h2 = bcast2(sH[k]);
                const float* wr = sWf + k * 256 + c0f;
                ulonglong2 wa = *(const ulonglong2*)(wr);
                ulonglong2 wb = *(const ulonglong2*)(wr + 4);
                ulonglong2 wc = *(const ulonglong2*)(wr + 8);
                ulonglong2 wd = *(const ulonglong2*)(wr + 12);
                fma2(fac[0], h2, wa.x); fma2(fac[1], h2, wa.y);
                fma2(fac[2], h2, wb.x); fma2(fac[3], h2, wb.y);
                fma2(fac[4], h2, wc.x); fma2(fac[5], h2, wc.y);
                fma2(fac[6], h2, wd.x); fma2(fac[7], h2, wd.y);
            }
            float f[16];
            #pragma unroll
            for (int j = 0; j < 8; ++j) upk2(fac[j], f[2 * j], f[2 * j + 1]);
            float* hw = g_HID + blk * 8192 + l;
            #pragma unroll
            for (int j = 0; j < 16; ++j) {
                float z = f[j] + sBf[c0f + j];
                float u = 0.7978845608028654f * (z + 0.044715f * z * z * z);
                float e2u = __expf(2.0f * u);
                float th = 1.0f - 2.0f / (e2u + 1.0f);
                hw[(c0f + j) * 32] = 0.5f * z * (1.0f + th);
            }
        }
        __syncthreads();
        {   // PR: warp -> 4 cols, lane -> token; hid from gmem (coalesced)
            const int c0p = w * 4;
            unsigned long long pac[2] = {0, 0};
            const float* hg = g_HID + blk * 8192 + l;
            #pragma unroll 8
            for (int k = 0; k < 256; ++k) {
                unsigned long long h2 = bcast2(hg[k * 32]);
                ulonglong2 wv = *(const ulonglong2*)&sWp[k * 64 + c0p];
                fma2(pac[0], h2, wv.x); fma2(pac[1], h2, wv.y);
            }
            float p4[4];
            upk2(pac[0], p4[0], p4[1]); upk2(pac[1], p4[2], p4[3]);
            float4 bp4 = __ldg((const float4*)(bpr_ + c0p));
            float* xr = sX + l * 65 + c0p;
            xr[0] += 0.1f * (p4[0] + bp4.x);
            xr[1] += 0.1f * (p4[1] + bp4.y);
            xr[2] += 0.1f * (p4[2] + bp4.z);
            xr[3] += 0.1f * (p4[3] + bp4.w);
        }
        __syncthreads();
    }

    // ================= final LN -> out =================
    {
        float g0 = __ldg(lnfg_ + l), g1 = __ldg(lnfg_ + 32 + l);
        float b0 = __ldg(lnfb_ + l), b1 = __ldg(lnfb_ + 32 + l);
        #pragma unroll
        for (int t = 0; t < 2; ++t) {
            int lt = 2 * w + t;
            float x0 = sX[lt * 65 + l], x1 = sX[lt * 65 + 32 + l];
            float s1 = x0 + x1, s2 = x0 * x0 + x1 * x1;
            #pragma unroll
            for (int o = 16; o; o >>= 1) {
                s1 += __shfl_xor_sync(0xffffffffu, s1, o);
                s2 += __shfl_xor_sync(0xffffffffu, s2, o);
            }
            float mu = s1 * (1.f / 64.f);
            float rs = rsqrtf(s2 * (1.f / 64.f) - mu * mu + 1e-5f);
            out[(t0 + lt) * 64 + l]      = (x0 - mu) * rs * g0 + b0;
            out[(t0 + lt) * 64 + 32 + l] = (x1 - mu) * rs * g1 + b1;
        }
    }
}

extern "C" void kernel_launch(void* const* d_in, const int* in_sizes, int n_in,
                              void* d_out, int out_size)
{
    (void)in_sizes; (void)n_in; (void)out_size;
    cudaFuncSetAttribute(lt37349035606833_kernel,
                         cudaFuncAttributeMaxDynamicSharedMemorySize, SMEM_BYTES);
    lt37349035606833_kernel<<<GRID, NTHREADS, SMEM_BYTES>>>(
        (const int*)  d_in[0],  (const int*)  d_in[1],
        (const float*)d_in[2],  (const float*)d_in[3],
        (const float*)d_in[4],  (const float*)d_in[5],
        (const float*)d_in[6],  (const float*)d_in[7],
        (const float*)d_in[8],  (const float*)d_in[9],
        (const float*)d_in[10], (const float*)d_in[11],
        (const float*)d_in[12], (const float*)d_in[13],
        (const float*)d_in[14], (const float*)d_in[15],
        (const float*)d_in[16], (const float*)d_in[17],
        (const float*)d_in[18], (const float*)d_in[19],
        (const float*)d_in[20], (const float*)d_in[21],
        (float*)d_out);
}